// round 8
// baseline (speedup 1.0000x reference)
#include <cuda_runtime.h>

// KMeansProbSampler: 8 iterations of weighted k-means scatter on a 1024x1024
// heatmap with 128 clusters.
//
// R8: single persistent kernel. R5/R7 showed a ~40us per-launch floor
// independent of inner-loop work, so all 8 iterations run inside ONE kernel
// with manual grid barriers (512 CTAs, guaranteed co-resident at <=4/SM via
// __launch_bounds__(256,4); barriers use monotone counters -> graph-replay
// safe, no reset races). 7 distinct inter-iteration buffers (no address reuse
// within a launch -> no L1 staleness; buffers re-zeroed post-final-barrier
// for the next replay).
//
// Math core (unchanged from R7, rel_err ~2e-4):
//   key_k(r,c) = fmaf(c, -2cc_k, fmaf(r, -2cr_k, n_k)), n_k = cr^2+cc^2
//   (shifted squared distance, argmin-invariant shift; linear in r,c and fma
//   is correctly rounded -> rectangle min/max at the 4 corners with the
//   identical fmaf composition as the scan).
// Per warp (8x16 sub-tile of a 32x32 tile): corner keys per cluster,
//   UB = min_k max_corner -> keep k iff min_corner <= UB (winner+ties kept),
//   ballot-compact ascending; per-pixel scan strict '<' ascending (lowest
//   index on ties = argmin). Exact d2 for winner; w = h*min(1,rsqrt(d2)).
//   Run-combined shared atomics; one global flush per CTA per iteration.

#define HH 1024
#define WW 1024
#define CC 128
#define NITER 8
#define PX 4
#define TPB 256
#define NWARP 8
#define BT 32
#define GRID 512
#define NTILES ((HH / BT) * (WW / BT))   // 1024

__device__ float    g_bufs[NITER - 1][CC * 2];   // zero-init; re-zeroed in-kernel
__device__ unsigned g_bcnt[NITER];               // monotone barrier counters

__device__ __forceinline__ void grid_bar(int idx) {
    __syncthreads();
    if (threadIdx.x == 0) {
        __threadfence();
        unsigned v   = atomicAdd(&g_bcnt[idx], 1u);
        unsigned tgt = (v / GRID + 1u) * GRID;   // monotone: replay-safe
        volatile unsigned* p = &g_bcnt[idx];
        while (*p < tgt) __nanosleep(64);
        __threadfence();
    }
    __syncthreads();
}

__global__ __launch_bounds__(TPB, 4) void kmeans_all_kernel(
    const float* __restrict__ clusters0,  // [C,2] initial (row, col)
    const float* __restrict__ heat,       // [H,W]
    float* __restrict__ out)              // [C,2] final sums
{
    __shared__ __align__(16) float4 sh_key[CC];          // (n, -2cr, -2cc, idx)
    __shared__ __align__(16) float4 sh_surv[NWARP][CC];  // compacted per warp
    __shared__ float2 sh_pos[CC];                        // (cr, cc)
    __shared__ float  sacc[CC * 2];

    const int t    = threadIdx.x;
    const int w    = t >> 5;
    const int lane = t & 31;
    const int b    = blockIdx.x;

    if (b == 0) out[t] = 0.0f;   // iter-7 target; ordered by 7 grid barriers

    for (int it = 0; it < NITER; it++) {
        const float* cur = (it == 0) ? clusters0 : g_bufs[it - 1];
        float*       nxt = (it == NITER - 1) ? out : g_bufs[it];

        if (t < CC) {
            float cr = cur[2 * t];
            float cc = cur[2 * t + 1];
            float n  = fmaf(cr, cr, cc * cc);
            sh_key[t] = make_float4(n, -2.0f * cr, -2.0f * cc, __int_as_float(t));
            sh_pos[t] = make_float2(cr, cc);
        }
        sacc[t] = 0.0f;
        __syncthreads();

        for (int tile = b; tile < NTILES; tile += GRID) {
            const int ty  = tile >> 5;
            const int tx  = tile & 31;
            // warp sub-tile: 8 rows x 16 cols; warps 4(rows) x 2(cols)
            const int wr0 = (ty << 5) + ((w >> 1) << 3);
            const int wc0 = (tx << 5) + ((w & 1) << 4);
            const int prow = wr0 + (lane >> 2);
            const int pcol = wc0 + ((lane & 3) << 2);
            const float rf = (float)prow;

            // ---- per-warp 2D pruning: 4 clusters per lane ----
            const float rLo = (float)wr0, rHi = (float)(wr0 + 7);
            const float cLo = (float)wc0, cHi = (float)(wc0 + 15);

            float4 cl[4];
            float  mn[4];
            float  ubl = 3.4e38f;
#pragma unroll
            for (int q = 0; q < 4; q++) {
                float4 k = sh_key[lane + 32 * q];
                cl[q] = k;
                float bLo = fmaf(rLo, k.y, k.x);
                float bHi = fmaf(rHi, k.y, k.x);
                float k00 = fmaf(cLo, k.z, bLo);
                float k01 = fmaf(cHi, k.z, bLo);
                float k10 = fmaf(cLo, k.z, bHi);
                float k11 = fmaf(cHi, k.z, bHi);
                mn[q]    = fminf(fminf(k00, k01), fminf(k10, k11));
                float mx = fmaxf(fmaxf(k00, k01), fmaxf(k10, k11));
                ubl = fminf(ubl, mx);
            }
            float ub = ubl;
#pragma unroll
            for (int off = 16; off; off >>= 1)
                ub = fminf(ub, __shfl_xor_sync(0xffffffffu, ub, off));

            int base = 0;
#pragma unroll
            for (int q = 0; q < 4; q++) {          // ascending q, ascending lane
                bool     p   = (mn[q] <= ub);      // non-strict: ties survive
                unsigned bal = __ballot_sync(0xffffffffu, p);
                int      pos = base + __popc(bal & ((1u << lane) - 1u));
                if (p) sh_surv[w][pos] = cl[q];
                base += __popc(bal);
            }
            const int nsurv = base;
            __syncwarp();

            // ---- per-pixel scan over survivors ----
            const float cf0 = (float)pcol;
            const float cfs[PX] = {cf0, cf0 + 1.0f, cf0 + 2.0f, cf0 + 3.0f};
            float4 hv = *reinterpret_cast<const float4*>(heat + prow * WW + pcol);
            const float heats[PX] = {hv.x, hv.y, hv.z, hv.w};

            float bm0 = 3.4e38f, bm1 = 3.4e38f, bm2 = 3.4e38f, bm3 = 3.4e38f;
            float bf0 = 0.0f, bf1 = 0.0f, bf2 = 0.0f, bf3 = 0.0f;
            for (int i = 0; i < nsurv; i++) {
                float4 s  = sh_surv[w][i];
                float  b2 = fmaf(rf, s.y, s.x);
                float  k0 = fmaf(cfs[0], s.z, b2);
                float  k1 = fmaf(cfs[1], s.z, b2);
                float  k2 = fmaf(cfs[2], s.z, b2);
                float  k3 = fmaf(cfs[3], s.z, b2);
                if (k0 < bm0) { bm0 = k0; bf0 = s.w; }  // strict '<': lowest idx
                if (k1 < bm1) { bm1 = k1; bf1 = s.w; }
                if (k2 < bm2) { bm2 = k2; bf2 = s.w; }
                if (k3 < bm3) { bm3 = k3; bf3 = s.w; }
            }
            const int bests[PX] = { __float_as_int(bf0), __float_as_int(bf1),
                                    __float_as_int(bf2), __float_as_int(bf3) };

            // ---- epilogue: exact d2, run-combined shared atomics ----
            int   curBest = -1;
            float ws = 0.0f, wc = 0.0f;
#pragma unroll
            for (int j = 0; j < PX; j++) {
                int    best = bests[j];
                float2 p    = sh_pos[best];
                float  dr   = rf - p.x;
                float  dc   = cfs[j] - p.y;
                float  d2   = fmaf(dr, dr, dc * dc);
                float  wgt  = heats[j] * fminf(1.0f, rsqrtf(d2));
                if (best == curBest) {
                    ws += wgt;
                    wc  = fmaf(wgt, cfs[j], wc);
                } else {
                    if (curBest >= 0) {
                        atomicAdd(&sacc[2 * curBest],     ws * rf);
                        atomicAdd(&sacc[2 * curBest + 1], wc);
                    }
                    curBest = best;
                    ws = wgt;
                    wc = wgt * cfs[j];
                }
            }
            atomicAdd(&sacc[2 * curBest],     ws * rf);
            atomicAdd(&sacc[2 * curBest + 1], wc);

            __syncwarp();   // sh_surv reused next tile (warp-private rows)
        }

        __syncthreads();
        atomicAdd(&nxt[t], sacc[t]);   // one flush per CTA per iteration
        grid_bar(it);
    }

    // re-zero inter-iteration buffers for the next graph replay
    // (all reads of g_bufs completed before the final barrier)
    if (b < NITER - 1) g_bufs[b][t] = 0.0f;
}

extern "C" void kernel_launch(void* const* d_in, const int* in_sizes, int n_in,
                              void* d_out, int out_size)
{
    const float* clusters = (const float*)d_in[0];
    const float* heat     = (const float*)d_in[1];
    if (in_sizes[0] != CC * 2) {  // robustness to metadata order
        const float* tmp = clusters; clusters = heat; heat = tmp;
    }
    kmeans_all_kernel<<<GRID, TPB>>>(clusters, heat, (float*)d_out);
}

// round 9
// speedup vs baseline: 1.6622x; 1.6622x over previous
#include <cuda_runtime.h>

// KMeansProbSampler: 8 iterations of weighted k-means scatter on a 1024x1024
// heatmap with 128 clusters.
//
// R9 = R7 + partial-buffer scatter (L2 atomic-chain fix).
//   R7's final flush sent 1024 same-address RED ops per output element
//   (~27 cyc/op serialized at the LTS atomic ALU -> ~16us drain tail,
//   invisible to issue/occupancy metrics). Now each CTA scatters into 1 of
//   NPART=16 partial buffers (chain depth 64, ~1us drain). A 1-CTA prep
//   kernel per iteration reduces prev partials -> pos[256] and zeroes the
//   next partials; a final tiny kernel reduces partials -> d_out.
//
// Math core (unchanged from R7, rel_err ~2e-4):
//   key_k(r,c) = fmaf(c, -2cc_k, fmaf(r, -2cr_k, n_k)), n_k = cr^2+cc^2
//   (shifted squared distance; argmin-invariant shift; linear in r,c and fma
//   is correctly rounded -> rectangle min/max at the 4 corners with the
//   identical fmaf composition as the scan).
// Per warp (8x16 sub-tile of a 32x32 tile): corner keys per cluster,
//   UB = min_k max_corner -> keep k iff min_corner <= UB (winner+ties kept),
//   ballot-compact ascending; per-pixel scan strict '<' ascending (lowest
//   index on ties = argmin). Exact d2 for winner; w = h*min(1,rsqrt(d2)).
//   Run-combined shared atomics, then per-CTA flush to its partial buffer.

#define HH 1024
#define WW 1024
#define CC 128
#define NITER 8
#define PX 4
#define TPB 256
#define NWARP (TPB / 32)
#define BT 32
#define NPART 16

__device__ float g_part[2][NPART][CC * 2];   // double-buffered partial sums
__device__ float g_pos[CC * 2];              // reduced positions for this iter

// prep: pos <- reduce(src over npart buffers); zero the partials at `zp`
__global__ void prep_kernel(const float* __restrict__ src, int npart,
                            float* __restrict__ pos, float* __restrict__ zp)
{
    const int t = threadIdx.x;          // 256 threads
    float s = 0.0f;
    for (int p = 0; p < npart; p++) s += src[p * (CC * 2) + t];
    pos[t] = s;
    float4* z4 = reinterpret_cast<float4*>(zp);
#pragma unroll
    for (int i = 0; i < NPART * (CC * 2) / 4 / TPB; i++)
        z4[i * TPB + t] = make_float4(0.f, 0.f, 0.f, 0.f);
}

__global__ void final_kernel(const float* __restrict__ src,
                             float* __restrict__ out)
{
    const int t = threadIdx.x;
    float s = 0.0f;
#pragma unroll
    for (int p = 0; p < NPART; p++) s += src[p * (CC * 2) + t];
    out[t] = s;
}

__global__ __launch_bounds__(TPB) void kmeans_iter_kernel(
    const float* __restrict__ pos_in,     // [C*2] current positions
    const float* __restrict__ heat,       // [H,W]
    float* __restrict__ part)             // [NPART][C*2] scatter target (zeroed)
{
    __shared__ __align__(16) float4 sh_surv[NWARP][CC];  // (n,-2cr,-2cc,idx)
    __shared__ float2 sh_pos[CC];                        // (cr, cc)
    __shared__ float  sacc[CC * 2];

    const int t    = threadIdx.x;
    const int w    = t >> 5;
    const int lane = t & 31;

    const int r0 = blockIdx.y * BT;
    const int c0 = blockIdx.x * BT;
    const int wr0 = r0 + (w >> 1) * 8;
    const int wc0 = c0 + (w & 1) * 16;
    const int   prow = wr0 + (lane >> 2);
    const int   pcol = wc0 + (lane & 3) * PX;
    const float rf   = (float)prow;

    if (t < CC) {
        sh_pos[t] = make_float2(pos_in[2 * t], pos_in[2 * t + 1]);
    }
    sacc[t] = 0.0f;
    __syncthreads();

    // ---- per-warp 2D pruning: 4 clusters per lane ----
    const float rLo = (float)wr0, rHi = (float)(wr0 + 7);
    const float cLo = (float)wc0, cHi = (float)(wc0 + 15);

    float3 cl[4];
    float  mn[4];
    float  ubl = 3.4e38f;
#pragma unroll
    for (int q = 0; q < 4; q++) {
        int    k  = lane + 32 * q;
        float2 p  = sh_pos[k];
        float  n  = fmaf(p.x, p.x, p.y * p.y);
        float  m2r = -2.0f * p.x;
        float  m2c = -2.0f * p.y;
        cl[q] = make_float3(n, m2r, m2c);
        float bLo = fmaf(rLo, m2r, n);
        float bHi = fmaf(rHi, m2r, n);
        float k00 = fmaf(cLo, m2c, bLo);
        float k01 = fmaf(cHi, m2c, bLo);
        float k10 = fmaf(cLo, m2c, bHi);
        float k11 = fmaf(cHi, m2c, bHi);
        mn[q]     = fminf(fminf(k00, k01), fminf(k10, k11));
        float mx  = fmaxf(fmaxf(k00, k01), fmaxf(k10, k11));
        ubl = fminf(ubl, mx);
    }
    float ub = ubl;
#pragma unroll
    for (int off = 16; off; off >>= 1)
        ub = fminf(ub, __shfl_xor_sync(0xffffffffu, ub, off));

    int base = 0;
#pragma unroll
    for (int q = 0; q < 4; q++) {                 // ascending q, ascending lane
        bool     p   = (mn[q] <= ub);             // non-strict: ties survive
        unsigned bal = __ballot_sync(0xffffffffu, p);
        int      pos = base + __popc(bal & ((1u << lane) - 1u));
        if (p) {
            sh_surv[w][pos] = make_float4(cl[q].x, cl[q].y, cl[q].z,
                                          __int_as_float(lane + 32 * q));
        }
        base += __popc(bal);
    }
    const int nsurv = base;
    __syncwarp();

    // ---- per-pixel scan over survivors ----
    const float cf0 = (float)pcol;
    const float cfs[PX] = {cf0, cf0 + 1.0f, cf0 + 2.0f, cf0 + 3.0f};
    float4 hv = *reinterpret_cast<const float4*>(heat + prow * WW + pcol);
    const float heats[PX] = {hv.x, hv.y, hv.z, hv.w};

    float bm0 = 3.4e38f, bm1 = 3.4e38f, bm2 = 3.4e38f, bm3 = 3.4e38f;
    float bf0 = 0.0f, bf1 = 0.0f, bf2 = 0.0f, bf3 = 0.0f;
    for (int i = 0; i < nsurv; i++) {
        float4 s  = sh_surv[w][i];
        float  b2 = fmaf(rf, s.y, s.x);
        float  k0 = fmaf(cfs[0], s.z, b2);
        float  k1 = fmaf(cfs[1], s.z, b2);
        float  k2 = fmaf(cfs[2], s.z, b2);
        float  k3 = fmaf(cfs[3], s.z, b2);
        if (k0 < bm0) { bm0 = k0; bf0 = s.w; }   // strict '<': lowest idx wins
        if (k1 < bm1) { bm1 = k1; bf1 = s.w; }
        if (k2 < bm2) { bm2 = k2; bf2 = s.w; }
        if (k3 < bm3) { bm3 = k3; bf3 = s.w; }
    }
    const int bests[PX] = { __float_as_int(bf0), __float_as_int(bf1),
                            __float_as_int(bf2), __float_as_int(bf3) };

    // ---- epilogue: exact d2 for winners, run-combined shared atomics ----
    int   curBest = -1;
    float ws = 0.0f, wc = 0.0f;
#pragma unroll
    for (int j = 0; j < PX; j++) {
        int    best = bests[j];
        float2 p    = sh_pos[best];
        float  dr   = rf - p.x;
        float  dc   = cfs[j] - p.y;
        float  d2   = fmaf(dr, dr, dc * dc);
        float  wgt  = heats[j] * fminf(1.0f, rsqrtf(d2));

        if (best == curBest) {
            ws += wgt;
            wc  = fmaf(wgt, cfs[j], wc);
        } else {
            if (curBest >= 0) {
                atomicAdd(&sacc[2 * curBest],     ws * rf);
                atomicAdd(&sacc[2 * curBest + 1], wc);
            }
            curBest = best;
            ws = wgt;
            wc = wgt * cfs[j];
        }
    }
    atomicAdd(&sacc[2 * curBest],     ws * rf);
    atomicAdd(&sacc[2 * curBest + 1], wc);

    __syncthreads();
    // per-CTA flush into its partial buffer: chain depth 1024/NPART = 64
    const int pp = (blockIdx.y * (WW / BT) + blockIdx.x) & (NPART - 1);
    atomicAdd(&part[pp * (CC * 2) + t], sacc[t]);
}

extern "C" void kernel_launch(void* const* d_in, const int* in_sizes, int n_in,
                              void* d_out, int out_size)
{
    const float* clusters = (const float*)d_in[0];
    const float* heat     = (const float*)d_in[1];
    if (in_sizes[0] != CC * 2) {  // robustness to metadata order
        const float* tmp = clusters; clusters = heat; heat = tmp;
    }

    float* part = nullptr;
    float* pos  = nullptr;
    cudaGetSymbolAddress((void**)&part, g_part);
    cudaGetSymbolAddress((void**)&pos,  g_pos);
    float* out = (float*)d_out;

    dim3 grid(WW / BT, HH / BT);
    for (int it = 0; it < NITER; it++) {
        float* cur = part + (it & 1) * NPART * (CC * 2);
        if (it == 0) {
            prep_kernel<<<1, TPB>>>(clusters, 1, pos, cur);
        } else {
            float* prev = part + ((it - 1) & 1) * NPART * (CC * 2);
            prep_kernel<<<1, TPB>>>(prev, NPART, pos, cur);
        }
        kmeans_iter_kernel<<<grid, TPB>>>(pos, heat, cur);
    }
    final_kernel<<<1, TPB>>>(part + ((NITER - 1) & 1) * NPART * (CC * 2), out);
}